// round 1
// baseline (speedup 1.0000x reference)
#include <cuda_runtime.h>
#include <math.h>
#include <stdint.h>

#define NPIX   65536      // 256*256
#define PCOUNT 1024       // 4 * 16 * 16 patches
#define NB     512        // 8^3 bins
#define SINK_EPS 1e-6f

// ---------------- scratch (static device globals; no allocation) ----------------
__device__ float    g_oklab[2][4 * 3 * NPIX];   // [img][b][c][h][w]
__device__ unsigned g_mm[12];                   // [0:6) min enc (img,c), [6:12) max enc
__device__ float    g_hist[2][PCOUNT * NB];     // normalized (counts/256)
__device__ float    g_u[PCOUNT * NB];
__device__ float    g_v[PCOUNT * NB];
__device__ float    g_K[NB * NB];
__device__ float    g_KC[NB * NB];              // K * cost
__device__ float    g_emd[PCOUNT];

// ---------------- helpers ----------------
__device__ __forceinline__ unsigned fenc(float f) {
    unsigned u = __float_as_uint(f);
    return (u & 0x80000000u) ? ~u : (u | 0x80000000u);
}
__device__ __forceinline__ float fdec(unsigned u) {
    return __uint_as_float((u & 0x80000000u) ? (u ^ 0x80000000u) : ~u);
}
__device__ __forceinline__ float srgb_lin(float x) {
    x = fminf(fmaxf(x, 0.0f), 1.0f);
    return (x <= 0.04045f) ? x * (1.0f / 12.92f)
                           : powf((x + 0.055f) * (1.0f / 1.055f), 2.4f);
}
// lo/hi per image per channel, with the narrow-range widening
__device__ __forceinline__ void get_lohi(int img, float* lo, float* hi) {
#pragma unroll
    for (int c = 0; c < 3; c++) {
        float l = fdec(g_mm[img * 3 + c]) - 0.01f;
        float h = fdec(g_mm[6 + img * 3 + c]) + 0.01f;
        if (h - l < 1e-4f) { l -= 0.05f; h += 0.05f; }
        lo[c] = l; hi[c] = h;
    }
}

// ---------------- init: u=1, emd=0, minmax sentinels ----------------
__global__ void init_kernel() {
    int idx = blockIdx.x * blockDim.x + threadIdx.x;   // grid sized exactly PCOUNT*NB
    g_u[idx] = 1.0f;
    if (idx < PCOUNT) g_emd[idx] = 0.0f;
    if (idx < 6) g_mm[idx] = 0xFFFFFFFFu;
    else if (idx < 12) g_mm[idx] = 0u;
}

// ---------------- sRGB -> OKLab + per-channel global min/max ----------------
__global__ void oklab_kernel(const float* __restrict__ ref, const float* __restrict__ tgt) {
    const int img = blockIdx.y;
    const float* __restrict__ in = img ? tgt : ref;
    float* __restrict__ outp = g_oklab[img];
    float mn0 = 1e30f, mn1 = 1e30f, mn2 = 1e30f;
    float mx0 = -1e30f, mx1 = -1e30f, mx2 = -1e30f;

    for (int idx = blockIdx.x * blockDim.x + threadIdx.x; idx < 4 * NPIX;
         idx += gridDim.x * blockDim.x) {
        int b = idx >> 16;
        int hw = idx & 65535;
        int base = b * 3 * NPIX + hw;
        float r  = srgb_lin(in[base]);
        float g  = srgb_lin(in[base + NPIX]);
        float bl = srgb_lin(in[base + 2 * NPIX]);
        float l = 0.4122214708f * r + 0.5363325363f * g + 0.0514459929f * bl;
        float m = 0.2119034982f * r + 0.6806995451f * g + 0.1073969566f * bl;
        float s = 0.0883024619f * r + 0.2817188376f * g + 0.6299787005f * bl;
        l = fmaxf(l, 0.0f); m = fmaxf(m, 0.0f); s = fmaxf(s, 0.0f);
        float lg = (l > 0.0f) ? cbrtf(fmaxf(l, 1e-12f)) : 0.0f;
        float mg = (m > 0.0f) ? cbrtf(fmaxf(m, 1e-12f)) : 0.0f;
        float sg = (s > 0.0f) ? cbrtf(fmaxf(s, 1e-12f)) : 0.0f;
        float L = 0.2104542553f * lg + 0.793617785f  * mg - 0.0040720468f * sg;
        float A = 1.9779984951f * lg - 2.428592205f  * mg + 0.4505937099f * sg;
        float B = 0.0259040371f * lg + 0.7827717662f * mg - 0.808675766f  * sg;
        outp[base] = L; outp[base + NPIX] = A; outp[base + 2 * NPIX] = B;
        mn0 = fminf(mn0, L); mx0 = fmaxf(mx0, L);
        mn1 = fminf(mn1, A); mx1 = fmaxf(mx1, A);
        mn2 = fminf(mn2, B); mx2 = fmaxf(mx2, B);
    }
#pragma unroll
    for (int o = 16; o > 0; o >>= 1) {
        mn0 = fminf(mn0, __shfl_down_sync(0xffffffffu, mn0, o));
        mn1 = fminf(mn1, __shfl_down_sync(0xffffffffu, mn1, o));
        mn2 = fminf(mn2, __shfl_down_sync(0xffffffffu, mn2, o));
        mx0 = fmaxf(mx0, __shfl_down_sync(0xffffffffu, mx0, o));
        mx1 = fmaxf(mx1, __shfl_down_sync(0xffffffffu, mx1, o));
        mx2 = fmaxf(mx2, __shfl_down_sync(0xffffffffu, mx2, o));
    }
    if ((threadIdx.x & 31) == 0) {
        atomicMin(&g_mm[img * 3 + 0], fenc(mn0));
        atomicMin(&g_mm[img * 3 + 1], fenc(mn1));
        atomicMin(&g_mm[img * 3 + 2], fenc(mn2));
        atomicMax(&g_mm[6 + img * 3 + 0], fenc(mx0));
        atomicMax(&g_mm[6 + img * 3 + 1], fenc(mx1));
        atomicMax(&g_mm[6 + img * 3 + 2], fenc(mx2));
    }
}

// ---------------- build K = exp(-cost/REG) and KC = K*cost on averaged grid ----------------
__global__ void buildK_kernel() {
    int i = blockIdx.x, j = threadIdx.x;
    float lor[3], hir[3], lot[3], hit[3];
    get_lohi(0, lor, hir);
    get_lohi(1, lot, hit);
    float base[3], step[3];
#pragma unroll
    for (int c = 0; c < 3; c++) {
        base[c] = (lor[c] + lot[c]) * 0.5f;
        step[c] = ((hir[c] - lor[c]) + (hit[c] - lot[c])) * 0.5f * 0.125f;
    }
    int i0 = i >> 6, i1 = (i >> 3) & 7, i2 = i & 7;
    int j0 = j >> 6, j1 = (j >> 3) & 7, j2 = j & 7;
    float d0 = (base[0] + step[0] * (i0 + 0.5f)) - (base[0] + step[0] * (j0 + 0.5f));
    float d1 = (base[1] + step[1] * (i1 + 0.5f)) - (base[1] + step[1] * (j1 + 0.5f));
    float d2 = (base[2] + step[2] * (i2 + 0.5f)) - (base[2] + step[2] * (j2 + 0.5f));
    float dd = d0 * d0 + d1 * d1 + d2 * d2;
    float cost = (dd > 0.0f) ? sqrtf(dd) : 0.0f;
    float Kv = expf(-cost * 10.0f);        // REG = 0.1
    g_K[i * NB + j]  = Kv;
    g_KC[i * NB + j] = Kv * cost;
}

// ---------------- per-patch histograms (separable nearest-center binning) ----------------
__global__ void hist_kernel() {
    const int img = blockIdx.y, p = blockIdx.x, t = threadIdx.x;
    __shared__ float h[NB];
    __shared__ float lo_s[3], inv_s[3];
    if (t == 0) {
        float lo[3], hi[3];
        get_lohi(img, lo, hi);
#pragma unroll
        for (int c = 0; c < 3; c++) { lo_s[c] = lo[c]; inv_s[c] = 8.0f / (hi[c] - lo[c]); }
    }
    h[t] = 0.0f; h[t + 256] = 0.0f;
    __syncthreads();

    int b = p >> 8, ph = (p >> 4) & 15, pw = p & 15;
    int py = t >> 4, px = t & 15;
    int hh = (ph << 4) + py, ww = (pw << 4) + px;
    int base = b * 3 * NPIX + hh * 256 + ww;
    const float* ok = g_oklab[img];
    float xL = ok[base], xA = ok[base + NPIX], xB = ok[base + 2 * NPIX];
    int i0 = (int)floorf((xL - lo_s[0]) * inv_s[0]); i0 = min(7, max(0, i0));
    int i1 = (int)floorf((xA - lo_s[1]) * inv_s[1]); i1 = min(7, max(0, i1));
    int i2 = (int)floorf((xB - lo_s[2]) * inv_s[2]); i2 = min(7, max(0, i2));
    atomicAdd(&h[(i0 << 6) | (i1 << 3) | i2], 1.0f);
    __syncthreads();

    float* dst = &g_hist[img][p * NB];
    dst[t]       = h[t]       * (1.0f / 256.0f);   // normalized (sum is exactly 256)
    dst[t + 256] = h[t + 256] * (1.0f / 256.0f);
}

// ---------------- sinkhorn GEMM: out = numer / (A@K + eps), or final EMD ----------------
// mode 0: v = ht / (u@K + eps);  mode 1: u = hr / (v@K + eps);  mode 2: emd += u . (v@KC)
__global__ void sink_kernel(int mode) {
    __shared__ float sm[2048];
    float* As = sm;            // [16][64], As[k*64+m]
    float* Bs = sm + 1024;     // [16][64]

    const float* Ap; const float* numer; float* outp; const float* Km;
    if (mode == 0)      { Ap = g_u; numer = g_hist[1]; outp = g_v; Km = g_K;  }
    else if (mode == 1) { Ap = g_v; numer = g_hist[0]; outp = g_u; Km = g_K;  }
    else                { Ap = g_v; numer = nullptr;   outp = nullptr; Km = g_KC; }

    const int tid = threadIdx.x;
    const int tx = tid & 15, ty = tid >> 4;
    const int row0 = blockIdx.y * 64, col0 = blockIdx.x * 64;
    const int lr = tid >> 2, lk = (tid & 3) << 2;   // A tile loader
    const int bk = tid >> 4, bn = (tid & 15) << 2;  // B tile loader

    float acc[4][4] = {};
    const float* Ag = Ap + (row0 + lr) * NB + lk;
    const float* Bg = Km + bk * NB + col0 + bn;

    for (int k0 = 0; k0 < NB; k0 += 16) {
        float4 a4 = *(const float4*)(Ag + k0);
        float4 b4 = *(const float4*)(Bg + k0 * NB);
        __syncthreads();
        As[(lk + 0) * 64 + lr] = a4.x;
        As[(lk + 1) * 64 + lr] = a4.y;
        As[(lk + 2) * 64 + lr] = a4.z;
        As[(lk + 3) * 64 + lr] = a4.w;
        *(float4*)(Bs + bk * 64 + bn) = b4;
        __syncthreads();
#pragma unroll
        for (int kk = 0; kk < 16; kk++) {
            float4 av = *(const float4*)(As + kk * 64 + ty * 4);
            float4 bv = *(const float4*)(Bs + kk * 64 + tx * 4);
            acc[0][0] += av.x * bv.x; acc[0][1] += av.x * bv.y;
            acc[0][2] += av.x * bv.z; acc[0][3] += av.x * bv.w;
            acc[1][0] += av.y * bv.x; acc[1][1] += av.y * bv.y;
            acc[1][2] += av.y * bv.z; acc[1][3] += av.y * bv.w;
            acc[2][0] += av.z * bv.x; acc[2][1] += av.z * bv.y;
            acc[2][2] += av.z * bv.z; acc[2][3] += av.z * bv.w;
            acc[3][0] += av.w * bv.x; acc[3][1] += av.w * bv.y;
            acc[3][2] += av.w * bv.z; acc[3][3] += av.w * bv.w;
        }
    }

    if (mode != 2) {
#pragma unroll
        for (int i = 0; i < 4; i++) {
            int r = row0 + ty * 4 + i;
#pragma unroll
            for (int j = 0; j < 4; j++) {
                int c = col0 + tx * 4 + j;
                outp[r * NB + c] = numer[r * NB + c] / (acc[i][j] + SINK_EPS);
            }
        }
    } else {
        // emd[r] += sum_c u[r,c] * (v@KC)[r,c]
        float s[4];
#pragma unroll
        for (int i = 0; i < 4; i++) {
            int r = row0 + ty * 4 + i;
            const float* ur = g_u + r * NB + col0 + tx * 4;
            s[i] = acc[i][0] * ur[0] + acc[i][1] * ur[1]
                 + acc[i][2] * ur[2] + acc[i][3] * ur[3];
        }
        __syncthreads();
#pragma unroll
        for (int i = 0; i < 4; i++) sm[(ty * 4 + i) * 16 + tx] = s[i];
        __syncthreads();
        if (tid < 64) {
            float tot = 0.0f;
#pragma unroll
            for (int q = 0; q < 16; q++) tot += sm[tid * 16 + q];
            atomicAdd(&g_emd[row0 + tid], tot);
        }
    }
}

// ---------------- half-pixel bilinear upsample 16x16 -> 256x256 ----------------
__global__ void upsample_kernel(float* __restrict__ out) {
    int idx = blockIdx.x * blockDim.x + threadIdx.x;
    if (idx >= 4 * NPIX) return;
    int b = idx >> 16, y = (idx >> 8) & 255, x = idx & 255;
    float fy = (y + 0.5f) * 0.0625f - 0.5f;
    float fx = (x + 0.5f) * 0.0625f - 0.5f;
    int y0 = (int)floorf(fy); float wy = fy - (float)y0;
    int x0 = (int)floorf(fx); float wx = fx - (float)x0;
    int y0c = min(15, max(0, y0)), y1c = min(15, max(0, y0 + 1));
    int x0c = min(15, max(0, x0)), x1c = min(15, max(0, x0 + 1));
    const float* e = g_emd + b * 256;
    float v00 = e[y0c * 16 + x0c], v01 = e[y0c * 16 + x1c];
    float v10 = e[y1c * 16 + x0c], v11 = e[y1c * 16 + x1c];
    v00 = isfinite(v00) ? v00 : 0.0f;
    v01 = isfinite(v01) ? v01 : 0.0f;
    v10 = isfinite(v10) ? v10 : 0.0f;
    v11 = isfinite(v11) ? v11 : 0.0f;
    float t0 = v00 + (v01 - v00) * wx;
    float t1 = v10 + (v11 - v10) * wx;
    out[idx] = t0 + (t1 - t0) * wy;
}

// ---------------- launcher ----------------
extern "C" void kernel_launch(void* const* d_in, const int* in_sizes, int n_in,
                              void* d_out, int out_size) {
    (void)in_sizes; (void)n_in; (void)out_size;
    const float* ref = (const float*)d_in[0];
    const float* tgt = (const float*)d_in[1];
    float* out = (float*)d_out;

    init_kernel<<<PCOUNT, NB>>>();                      // 1024*512 threads == u size
    oklab_kernel<<<dim3(256, 2), 256>>>(ref, tgt);
    buildK_kernel<<<NB, NB>>>();
    hist_kernel<<<dim3(PCOUNT, 2), 256>>>();

    dim3 gg(NB / 64, PCOUNT / 64);                      // (8, 16) = 128 CTAs
    for (int it = 0; it < 20; it++) {
        sink_kernel<<<gg, 256>>>(0);                    // v-update
        sink_kernel<<<gg, 256>>>(1);                    // u-update
    }
    sink_kernel<<<gg, 256>>>(2);                        // emd accumulation

    upsample_kernel<<<(4 * NPIX + 255) / 256, 256>>>(out);
}

// round 4
// speedup vs baseline: 1.2055x; 1.2055x over previous
#include <cuda_runtime.h>
#include <math.h>
#include <stdint.h>

#define NPIX   65536      // 256*256
#define PCOUNT 1024       // 4 * 16 * 16 patches
#define NB     512        // 8^3 bins
#define SINK_EPS 1e-6f

#define BM 64
#define BN 64
#define BK 16

// ---------------- scratch (static device globals; no allocation) ----------------
__device__ float    g_oklab[2][4 * 3 * NPIX];   // [img][b][c][h][w]
__device__ unsigned g_mm[12];                   // [0:6) min enc (img,c), [6:12) max enc
__device__ float    g_hist[2][PCOUNT * NB];     // normalized (counts/256)
__device__ float    g_u[PCOUNT * NB];
__device__ float    g_v[PCOUNT * NB];
__device__ float    g_K[NB * NB];
__device__ float    g_KC[NB * NB];              // K * cost
__device__ float    g_emd[PCOUNT];

typedef unsigned long long ull;

// packed fp32x2 FMA: d = a*b + d (two independent lanes)
__device__ __forceinline__ void ffma2(ull& d, ull a, ull b) {
    asm("fma.rn.f32x2 %0, %1, %2, %0;" : "+l"(d) : "l"(a), "l"(b));
}
__device__ __forceinline__ ull dup_f32(float x) {
    ull r;
    unsigned u = __float_as_uint(x);
    asm("mov.b64 %0, {%1, %1};" : "=l"(r) : "r"(u));
    return r;
}
__device__ __forceinline__ float lo_f(ull p) { return __uint_as_float((unsigned)p); }
__device__ __forceinline__ float hi_f(ull p) { return __uint_as_float((unsigned)(p >> 32)); }

// ---------------- helpers ----------------
__device__ __forceinline__ unsigned fenc(float f) {
    unsigned u = __float_as_uint(f);
    return (u & 0x80000000u) ? ~u : (u | 0x80000000u);
}
__device__ __forceinline__ float fdec(unsigned u) {
    return __uint_as_float((u & 0x80000000u) ? (u ^ 0x80000000u) : ~u);
}
__device__ __forceinline__ float srgb_lin(float x) {
    x = fminf(fmaxf(x, 0.0f), 1.0f);
    return (x <= 0.04045f) ? x * (1.0f / 12.92f)
                           : powf((x + 0.055f) * (1.0f / 1.055f), 2.4f);
}
__device__ __forceinline__ void get_lohi(int img, float* lo, float* hi) {
#pragma unroll
    for (int c = 0; c < 3; c++) {
        float l = fdec(g_mm[img * 3 + c]) - 0.01f;
        float h = fdec(g_mm[6 + img * 3 + c]) + 0.01f;
        if (h - l < 1e-4f) { l -= 0.05f; h += 0.05f; }
        lo[c] = l; hi[c] = h;
    }
}

// ---------------- init: u=1, emd=0, minmax sentinels ----------------
__global__ void init_kernel() {
    int idx = blockIdx.x * blockDim.x + threadIdx.x;
    g_u[idx] = 1.0f;
    if (idx < PCOUNT) g_emd[idx] = 0.0f;
    if (idx < 6) g_mm[idx] = 0xFFFFFFFFu;
    else if (idx < 12) g_mm[idx] = 0u;
}

// ---------------- sRGB -> OKLab + per-channel global min/max ----------------
__global__ void oklab_kernel(const float* __restrict__ ref, const float* __restrict__ tgt) {
    const int img = blockIdx.y;
    const float* __restrict__ in = img ? tgt : ref;
    float* __restrict__ outp = g_oklab[img];
    float mn0 = 1e30f, mn1 = 1e30f, mn2 = 1e30f;
    float mx0 = -1e30f, mx1 = -1e30f, mx2 = -1e30f;

    for (int idx = blockIdx.x * blockDim.x + threadIdx.x; idx < 4 * NPIX;
         idx += gridDim.x * blockDim.x) {
        int b = idx >> 16;
        int hw = idx & 65535;
        int base = b * 3 * NPIX + hw;
        float r  = srgb_lin(in[base]);
        float g  = srgb_lin(in[base + NPIX]);
        float bl = srgb_lin(in[base + 2 * NPIX]);
        float l = 0.4122214708f * r + 0.5363325363f * g + 0.0514459929f * bl;
        float m = 0.2119034982f * r + 0.6806995451f * g + 0.1073969566f * bl;
        float s = 0.0883024619f * r + 0.2817188376f * g + 0.6299787005f * bl;
        l = fmaxf(l, 0.0f); m = fmaxf(m, 0.0f); s = fmaxf(s, 0.0f);
        float lg = (l > 0.0f) ? cbrtf(fmaxf(l, 1e-12f)) : 0.0f;
        float mg = (m > 0.0f) ? cbrtf(fmaxf(m, 1e-12f)) : 0.0f;
        float sg = (s > 0.0f) ? cbrtf(fmaxf(s, 1e-12f)) : 0.0f;
        float L = 0.2104542553f * lg + 0.793617785f  * mg - 0.0040720468f * sg;
        float A = 1.9779984951f * lg - 2.428592205f  * mg + 0.4505937099f * sg;
        float B = 0.0259040371f * lg + 0.7827717662f * mg - 0.808675766f  * sg;
        outp[base] = L; outp[base + NPIX] = A; outp[base + 2 * NPIX] = B;
        mn0 = fminf(mn0, L); mx0 = fmaxf(mx0, L);
        mn1 = fminf(mn1, A); mx1 = fmaxf(mx1, A);
        mn2 = fminf(mn2, B); mx2 = fmaxf(mx2, B);
    }
#pragma unroll
    for (int o = 16; o > 0; o >>= 1) {
        mn0 = fminf(mn0, __shfl_down_sync(0xffffffffu, mn0, o));
        mn1 = fminf(mn1, __shfl_down_sync(0xffffffffu, mn1, o));
        mn2 = fminf(mn2, __shfl_down_sync(0xffffffffu, mn2, o));
        mx0 = fmaxf(mx0, __shfl_down_sync(0xffffffffu, mx0, o));
        mx1 = fmaxf(mx1, __shfl_down_sync(0xffffffffu, mx1, o));
        mx2 = fmaxf(mx2, __shfl_down_sync(0xffffffffu, mx2, o));
    }
    if ((threadIdx.x & 31) == 0) {
        atomicMin(&g_mm[img * 3 + 0], fenc(mn0));
        atomicMin(&g_mm[img * 3 + 1], fenc(mn1));
        atomicMin(&g_mm[img * 3 + 2], fenc(mn2));
        atomicMax(&g_mm[6 + img * 3 + 0], fenc(mx0));
        atomicMax(&g_mm[6 + img * 3 + 1], fenc(mx1));
        atomicMax(&g_mm[6 + img * 3 + 2], fenc(mx2));
    }
}

// ---------------- build K = exp(-cost/REG) and KC = K*cost on averaged grid ----------------
__global__ void buildK_kernel() {
    int i = blockIdx.x, j = threadIdx.x;
    float lor[3], hir[3], lot[3], hit[3];
    get_lohi(0, lor, hir);
    get_lohi(1, lot, hit);
    float step[3];
#pragma unroll
    for (int c = 0; c < 3; c++) {
        step[c] = ((hir[c] - lor[c]) + (hit[c] - lot[c])) * 0.5f * 0.125f;
    }
    int i0 = i >> 6, i1 = (i >> 3) & 7, i2 = i & 7;
    int j0 = j >> 6, j1 = (j >> 3) & 7, j2 = j & 7;
    float d0 = step[0] * (float)(i0 - j0);
    float d1 = step[1] * (float)(i1 - j1);
    float d2 = step[2] * (float)(i2 - j2);
    float dd = d0 * d0 + d1 * d1 + d2 * d2;
    float cost = (dd > 0.0f) ? sqrtf(dd) : 0.0f;
    float Kv = expf(-cost * 10.0f);        // REG = 0.1
    g_K[i * NB + j]  = Kv;
    g_KC[i * NB + j] = Kv * cost;
}

// ---------------- per-patch histograms (separable nearest-center binning) ----------------
__global__ void hist_kernel() {
    const int img = blockIdx.y, p = blockIdx.x, t = threadIdx.x;
    __shared__ float h[NB];
    __shared__ float lo_s[3], inv_s[3];
    if (t == 0) {
        float lo[3], hi[3];
        get_lohi(img, lo, hi);
#pragma unroll
        for (int c = 0; c < 3; c++) { lo_s[c] = lo[c]; inv_s[c] = 8.0f / (hi[c] - lo[c]); }
    }
    h[t] = 0.0f; h[t + 256] = 0.0f;
    __syncthreads();

    int b = p >> 8, ph = (p >> 4) & 15, pw = p & 15;
    int py = t >> 4, px = t & 15;
    int hh = (ph << 4) + py, ww = (pw << 4) + px;
    int base = b * 3 * NPIX + hh * 256 + ww;
    const float* ok = g_oklab[img];
    float xL = ok[base], xA = ok[base + NPIX], xB = ok[base + 2 * NPIX];
    int i0 = (int)floorf((xL - lo_s[0]) * inv_s[0]); i0 = min(7, max(0, i0));
    int i1 = (int)floorf((xA - lo_s[1]) * inv_s[1]); i1 = min(7, max(0, i1));
    int i2 = (int)floorf((xB - lo_s[2]) * inv_s[2]); i2 = min(7, max(0, i2));
    atomicAdd(&h[(i0 << 6) | (i1 << 3) | i2], 1.0f);
    __syncthreads();

    float* dst = &g_hist[img][p * NB];
    dst[t]       = h[t]       * (1.0f / 256.0f);
    dst[t + 256] = h[t + 256] * (1.0f / 256.0f);
}

// ---------------- sinkhorn GEMM (double-buffered, f32x2 FMA, 8x4 micro) ----------------
// mode 0: v = ht / (u@K + eps);  mode 1: u = hr / (v@K + eps);  mode 2: emd += u . (v@KC)
__global__ void __launch_bounds__(128) sink_kernel(int mode) {
    __shared__ float As[2][BK][BM];     // [buf][k][m]   4KB x2
    __shared__ float Bs[2][BK][BN];     // [buf][k][n]   4KB x2
    __shared__ float red[BM][16];       // mode-2 reduction

    const float* Ap; const float* numer; float* outp; const float* Km;
    if (mode == 0)      { Ap = g_u; numer = g_hist[1]; outp = g_v; Km = g_K;  }
    else if (mode == 1) { Ap = g_v; numer = g_hist[0]; outp = g_u; Km = g_K;  }
    else                { Ap = g_v; numer = nullptr;   outp = nullptr; Km = g_KC; }

    const int tid = threadIdx.x;
    const int tx = tid & 15;            // 16 -> col0 = tx*4
    const int ty = tid >> 4;            // 8  -> rows ty*8 .. ty*8+7 (as 4 pairs)
    const int row0 = blockIdx.y * BM, col0 = blockIdx.x * BN;

    // A loader: row ra = tid>>1, k offset ka = (tid&1)*8 (2 float4 along k)
    const int ra = tid >> 1, ka = (tid & 1) * 8;
    // B loader: k row kb = tid>>3, n offset nb = (tid&7)*8 (2 float4 along n)
    const int kb = tid >> 3, nbo = (tid & 7) * 8;

    const float* Ag = Ap + (row0 + ra) * NB + ka;
    const float* Bg = Km + kb * NB + col0 + nbo;

    ull acc[4][4];                      // [row-pair][col]
#pragma unroll
    for (int i = 0; i < 4; i++)
#pragma unroll
        for (int j = 0; j < 4; j++) acc[i][j] = 0ull;

    // prologue: load chunk 0
    float4 a0 = *(const float4*)(Ag);
    float4 a1 = *(const float4*)(Ag + 4);
    float4 b0 = *(const float4*)(Bg);
    float4 b1 = *(const float4*)(Bg + 4);
    {
        float av[8] = {a0.x, a0.y, a0.z, a0.w, a1.x, a1.y, a1.z, a1.w};
#pragma unroll
        for (int j = 0; j < 8; j++) As[0][ka + j][ra] = av[j];
        *(float4*)(&Bs[0][kb][nbo]) = b0;
        *(float4*)(&Bs[0][kb][nbo + 4]) = b1;
    }
    __syncthreads();

    int buf = 0;
    for (int k0 = 0; k0 < NB / BK; k0++) {
        // prefetch next chunk
        if (k0 + 1 < NB / BK) {
            const float* Agn = Ag + (k0 + 1) * BK;
            const float* Bgn = Bg + (k0 + 1) * BK * NB;
            a0 = *(const float4*)(Agn);
            a1 = *(const float4*)(Agn + 4);
            b0 = *(const float4*)(Bgn);
            b1 = *(const float4*)(Bgn + 4);
        }
        // compute current chunk
#pragma unroll
        for (int kk = 0; kk < BK; kk++) {
            const ull* ap = (const ull*)(&As[buf][kk][ty * 8]);   // 4 packed row-pairs
            ull a0p = ap[0], a1p = ap[1], a2p = ap[2], a3p = ap[3];
            float4 bq = *(const float4*)(&Bs[buf][kk][tx * 4]);
            ull bb0 = dup_f32(bq.x), bb1 = dup_f32(bq.y);
            ull bb2 = dup_f32(bq.z), bb3 = dup_f32(bq.w);
            ffma2(acc[0][0], a0p, bb0); ffma2(acc[0][1], a0p, bb1);
            ffma2(acc[0][2], a0p, bb2); ffma2(acc[0][3], a0p, bb3);
            ffma2(acc[1][0], a1p, bb0); ffma2(acc[1][1], a1p, bb1);
            ffma2(acc[1][2], a1p, bb2); ffma2(acc[1][3], a1p, bb3);
            ffma2(acc[2][0], a2p, bb0); ffma2(acc[2][1], a2p, bb1);
            ffma2(acc[2][2], a2p, bb2); ffma2(acc[2][3], a2p, bb3);
            ffma2(acc[3][0], a3p, bb0); ffma2(acc[3][1], a3p, bb1);
            ffma2(acc[3][2], a3p, bb2); ffma2(acc[3][3], a3p, bb3);
        }
        // store next chunk to other buffer
        if (k0 + 1 < NB / BK) {
            int nbuf = buf ^ 1;
            float av[8] = {a0.x, a0.y, a0.z, a0.w, a1.x, a1.y, a1.z, a1.w};
#pragma unroll
            for (int j = 0; j < 8; j++) As[nbuf][ka + j][ra] = av[j];
            *(float4*)(&Bs[nbuf][kb][nbo]) = b0;
            *(float4*)(&Bs[nbuf][kb][nbo + 4]) = b1;
            __syncthreads();
            buf = nbuf;
        }
    }

    if (mode != 2) {
#pragma unroll
        for (int pr = 0; pr < 4; pr++) {
            int rlo = row0 + ty * 8 + pr * 2;
            int c = col0 + tx * 4;
            float4 nlo = *(const float4*)(numer + rlo * NB + c);
            float4 nhi = *(const float4*)(numer + (rlo + 1) * NB + c);
            float4 olo, ohi;
            olo.x = nlo.x / (lo_f(acc[pr][0]) + SINK_EPS);
            olo.y = nlo.y / (lo_f(acc[pr][1]) + SINK_EPS);
            olo.z = nlo.z / (lo_f(acc[pr][2]) + SINK_EPS);
            olo.w = nlo.w / (lo_f(acc[pr][3]) + SINK_EPS);
            ohi.x = nhi.x / (hi_f(acc[pr][0]) + SINK_EPS);
            ohi.y = nhi.y / (hi_f(acc[pr][1]) + SINK_EPS);
            ohi.z = nhi.z / (hi_f(acc[pr][2]) + SINK_EPS);
            ohi.w = nhi.w / (hi_f(acc[pr][3]) + SINK_EPS);
            *(float4*)(outp + rlo * NB + c) = olo;
            *(float4*)(outp + (rlo + 1) * NB + c) = ohi;
        }
    } else {
        // emd[r] += sum_c u[r,c] * (v@KC)[r,c]
        __syncthreads();
#pragma unroll
        for (int pr = 0; pr < 4; pr++) {
            int rlo = row0 + ty * 8 + pr * 2;
            int c = col0 + tx * 4;
            float4 ulo = *(const float4*)(g_u + rlo * NB + c);
            float4 uhi = *(const float4*)(g_u + (rlo + 1) * NB + c);
            float slo = lo_f(acc[pr][0]) * ulo.x + lo_f(acc[pr][1]) * ulo.y
                      + lo_f(acc[pr][2]) * ulo.z + lo_f(acc[pr][3]) * ulo.w;
            float shi = hi_f(acc[pr][0]) * uhi.x + hi_f(acc[pr][1]) * uhi.y
                      + hi_f(acc[pr][2]) * uhi.z + hi_f(acc[pr][3]) * uhi.w;
            red[ty * 8 + pr * 2][tx]     = slo;
            red[ty * 8 + pr * 2 + 1][tx] = shi;
        }
        __syncthreads();
        if (tid < BM) {
            float tot = 0.0f;
#pragma unroll
            for (int q = 0; q < 16; q++) tot += red[tid][q];
            atomicAdd(&g_emd[row0 + tid], tot);
        }
    }
}

// ---------------- half-pixel bilinear upsample 16x16 -> 256x256 ----------------
__global__ void upsample_kernel(float* __restrict__ out) {
    int idx = blockIdx.x * blockDim.x + threadIdx.x;
    if (idx >= 4 * NPIX) return;
    int b = idx >> 16, y = (idx >> 8) & 255, x = idx & 255;
    float fy = (y + 0.5f) * 0.0625f - 0.5f;
    float fx = (x + 0.5f) * 0.0625f - 0.5f;
    int y0 = (int)floorf(fy); float wy = fy - (float)y0;
    int x0 = (int)floorf(fx); float wx = fx - (float)x0;
    int y0c = min(15, max(0, y0)), y1c = min(15, max(0, y0 + 1));
    int x0c = min(15, max(0, x0)), x1c = min(15, max(0, x0 + 1));
    const float* e = g_emd + b * 256;
    float v00 = e[y0c * 16 + x0c], v01 = e[y0c * 16 + x1c];
    float v10 = e[y1c * 16 + x0c], v11 = e[y1c * 16 + x1c];
    v00 = isfinite(v00) ? v00 : 0.0f;
    v01 = isfinite(v01) ? v01 : 0.0f;
    v10 = isfinite(v10) ? v10 : 0.0f;
    v11 = isfinite(v11) ? v11 : 0.0f;
    float t0 = v00 + (v01 - v00) * wx;
    float t1 = v10 + (v11 - v10) * wx;
    out[idx] = t0 + (t1 - t0) * wy;
}

// ---------------- launcher ----------------
extern "C" void kernel_launch(void* const* d_in, const int* in_sizes, int n_in,
                              void* d_out, int out_size) {
    (void)in_sizes; (void)n_in; (void)out_size;
    const float* ref = (const float*)d_in[0];
    const float* tgt = (const float*)d_in[1];
    float* out = (float*)d_out;

    init_kernel<<<PCOUNT, NB>>>();
    oklab_kernel<<<dim3(256, 2), 256>>>(ref, tgt);
    buildK_kernel<<<NB, NB>>>();
    hist_kernel<<<dim3(PCOUNT, 2), 256>>>();

    dim3 gg(NB / BN, PCOUNT / BM);                      // (8, 16) = 128 CTAs
    for (int it = 0; it < 20; it++) {
        sink_kernel<<<gg, 128>>>(0);                    // v-update
        sink_kernel<<<gg, 128>>>(1);                    // u-update
    }
    sink_kernel<<<gg, 128>>>(2);                        // emd accumulation

    upsample_kernel<<<(4 * NPIX + 255) / 256, 256>>>(out);
}